// round 3
// baseline (speedup 1.0000x reference)
#include <cuda_runtime.h>
#include <stdint.h>

// Problem constants (match reference)
#define BATCH 8
#define SEQ   4096
#define NPOS  (BATCH * SEQ)     // 32768
#define SLOT  80                // floats per head slot
#define NTAB  16                // 8 heads x 2 orders
#define F4_PER_ROW (SLOT / 4)   // 20 float4 per row
#define THREADS (NTAB * F4_PER_ROW)  // 320

// table sizes: 8 x n=2 then 8 x n=3
__constant__ unsigned int c_sizes[16] = {
    6619u, 6637u, 6653u, 6659u, 6661u, 6673u, 6679u, 6689u,
    65521u, 65537u, 65539u, 65543u, 65551u, 65557u, 65563u, 65579u
};

struct Tables { const float* t[16]; };

__global__ __launch_bounds__(THREADS) void engram_kernel(
    const int* __restrict__ ids,      // [B, S] int32 (harness materializes int64 as int32)
    const int* __restrict__ seeds,    // [3, 8] int32
    Tables tp,
    float* __restrict__ out)          // [B, S, 1280] fp32
{
    const int pos = blockIdx.x;            // 0 .. NPOS-1
    const int s   = pos & (SEQ - 1);

    __shared__ const float* s_row[NTAB];

    if (threadIdx.x < NTAB) {
        const int head = threadIdx.x & 7;
        // suffix n-gram ids, left-padded with 0 (per batch row)
        const unsigned long long id0 = (unsigned long long)(unsigned int)ids[pos];
        const unsigned long long id1 = (s >= 1) ? (unsigned long long)(unsigned int)ids[pos - 1] : 0ull;

        unsigned long long h;
        if (threadIdx.x < 8) {
            // n=2: h = id[s-1]*seed[0][k] ^ id[s]*seed[1][k]
            h = (id1 * (unsigned long long)(unsigned int)seeds[head])
              ^ (id0 * (unsigned long long)(unsigned int)seeds[8 + head]);
        } else {
            // n=3: h = id[s-2]*seed[0][k] ^ id[s-1]*seed[1][k] ^ id[s]*seed[2][k]
            const unsigned long long id2 = (s >= 2) ? (unsigned long long)(unsigned int)ids[pos - 2] : 0ull;
            h = (id2 * (unsigned long long)(unsigned int)seeds[head])
              ^ (id1 * (unsigned long long)(unsigned int)seeds[8 + head])
              ^ (id0 * (unsigned long long)(unsigned int)seeds[16 + head]);
        }
        const unsigned int idx = (unsigned int)(h % (unsigned long long)c_sizes[threadIdx.x]);
        s_row[threadIdx.x] = tp.t[threadIdx.x] + (size_t)idx * SLOT;
    }
    __syncthreads();

    // 320 threads: thread t moves float4 #q of table #tab
    const int t   = threadIdx.x;
    const int tab = t / F4_PER_ROW;
    const int q   = t - tab * F4_PER_ROW;

    const float4 v = __ldg(((const float4*)s_row[tab]) + q);
    ((float4*)out)[(size_t)pos * (NTAB * F4_PER_ROW) + t] = v;
}

extern "C" void kernel_launch(void* const* d_in, const int* in_sizes, int n_in,
                              void* d_out, int out_size)
{
    const int* ids   = (const int*)d_in[0];
    const int* seeds = (const int*)d_in[1];

    Tables tp;
    #pragma unroll
    for (int i = 0; i < 16; i++) tp.t[i] = (const float*)d_in[2 + i];

    engram_kernel<<<NPOS, THREADS>>>(ids, seeds, tp, (float*)d_out);
}

// round 4
// speedup vs baseline: 3.3033x; 3.3033x over previous
#include <cuda_runtime.h>
#include <stdint.h>

#define SEQ   4096
#define NPOS  32768
#define SLOT  80
#define ROW_BYTES (SLOT * 4)            // 320
#define NTAB  16
#define P     8                          // positions per block
#define THREADS (P * NTAB)               // 128
#define STAGE_BYTES (P * NTAB * ROW_BYTES)  // 40960
#define NBLOCKS (NPOS / P)               // 4096

// table sizes: 8 x n=2 then 8 x n=3
__constant__ unsigned int c_sizes[16] = {
    6619u, 6637u, 6653u, 6659u, 6661u, 6673u, 6679u, 6689u,
    65521u, 65537u, 65539u, 65543u, 65551u, 65557u, 65563u, 65579u
};

struct Tables { const float* t[16]; };

__device__ __forceinline__ uint32_t smem_u32(const void* p) {
    uint32_t a;
    asm("{ .reg .u64 tmp; cvta.to.shared.u64 tmp, %1; cvt.u32.u64 %0, tmp; }"
        : "=r"(a) : "l"(p));
    return a;
}

__global__ __launch_bounds__(THREADS) void engram_kernel(
    const int* __restrict__ ids,      // [B, S] int32
    const int* __restrict__ seeds,    // [3, 8] int32
    Tables tp,
    float* __restrict__ out)          // [B, S, 1280] fp32
{
    __shared__ __align__(16) unsigned char stage[STAGE_BYTES];
    __shared__ __align__(8)  unsigned long long mbar;

    const int tid = threadIdx.x;
    const uint32_t mbar_a  = smem_u32(&mbar);
    const uint32_t stage_a = smem_u32(stage);

    if (tid == 0) {
        asm volatile("mbarrier.init.shared.b64 [%0], %1;"
                     :: "r"(mbar_a), "r"(1) : "memory");
    }
    __syncthreads();

    // one hash per thread: p = position-within-block, tab = table index
    const int p    = tid >> 4;
    const int tab  = tid & 15;
    const int head = tab & 7;
    const int pos  = blockIdx.x * P + p;
    const int s    = pos & (SEQ - 1);

    const unsigned long long id0 = (unsigned long long)(unsigned int)ids[pos];
    const unsigned long long id1 =
        (s >= 1) ? (unsigned long long)(unsigned int)ids[pos - 1] : 0ull;

    unsigned long long h;
    if (tab < 8) {
        // n=2: id[s-1]*seed[0][k] ^ id[s]*seed[1][k]
        h = (id1 * (unsigned long long)(unsigned int)seeds[head])
          ^ (id0 * (unsigned long long)(unsigned int)seeds[8 + head]);
    } else {
        // n=3: id[s-2]*seed[0][k] ^ id[s-1]*seed[1][k] ^ id[s]*seed[2][k]
        const unsigned long long id2 =
            (s >= 2) ? (unsigned long long)(unsigned int)ids[pos - 2] : 0ull;
        h = (id2 * (unsigned long long)(unsigned int)seeds[head])
          ^ (id1 * (unsigned long long)(unsigned int)seeds[8 + head])
          ^ (id0 * (unsigned long long)(unsigned int)seeds[16 + head]);
    }
    const unsigned int idx = (unsigned int)(h % (unsigned long long)c_sizes[tab]);

    // bulk-copy this row (320B) into the staging tile
    const char*    src = (const char*)tp.t[tab] + (size_t)idx * ROW_BYTES;
    const uint32_t dst = stage_a + (uint32_t)tid * ROW_BYTES;   // (p*16+tab)*320

    asm volatile(
        "cp.async.bulk.shared::cta.global.mbarrier::complete_tx::bytes "
        "[%0], [%1], %2, [%3];"
        :: "r"(dst), "l"(src), "r"((int)ROW_BYTES), "r"(mbar_a)
        : "memory");

    if (tid == 0) {
        // single arrival carrying the full expected-transaction count
        asm volatile("mbarrier.arrive.expect_tx.shared.b64 _, [%0], %1;"
                     :: "r"(mbar_a), "r"((int)STAGE_BYTES) : "memory");
        // wait for all 128 row copies to land
        asm volatile(
            "{\n\t"
            ".reg .pred P1;\n\t"
            "WAIT_%=:\n\t"
            "mbarrier.try_wait.parity.shared.b64 P1, [%0], 0, 0x989680;\n\t"
            "@P1 bra.uni DONE_%=;\n\t"
            "bra.uni WAIT_%=;\n\t"
            "DONE_%=:\n\t"
            "}"
            :: "r"(mbar_a) : "memory");

        // one contiguous 40KB bulk store: positions are contiguous in output
        char* gdst = (char*)out + (size_t)blockIdx.x * STAGE_BYTES;
        asm volatile(
            "cp.async.bulk.global.shared::cta.bulk_group [%0], [%1], %2;"
            :: "l"(gdst), "r"(stage_a), "r"((int)STAGE_BYTES)
            : "memory");
        asm volatile("cp.async.bulk.commit_group;" ::: "memory");
        asm volatile("cp.async.bulk.wait_group 0;" ::: "memory");
    }
}

extern "C" void kernel_launch(void* const* d_in, const int* in_sizes, int n_in,
                              void* d_out, int out_size)
{
    const int* ids   = (const int*)d_in[0];
    const int* seeds = (const int*)d_in[1];

    Tables tp;
    #pragma unroll
    for (int i = 0; i < 16; i++) tp.t[i] = (const float*)d_in[2 + i];

    engram_kernel<<<NBLOCKS, THREADS>>>(ids, seeds, tp, (float*)d_out);
}

// round 5
// speedup vs baseline: 3.3053x; 1.0006x over previous
#include <cuda_runtime.h>
#include <stdint.h>

#define SEQ   4096
#define NPOS  32768
#define SLOT  80
#define ROW_BYTES (SLOT * 4)                 // 320
#define NTAB  16
#define P     8                              // positions per chunk
#define THREADS (P * NTAB)                   // 128
#define CHUNK_BYTES (P * NTAB * ROW_BYTES)   // 40960
#define CHUNKS 8
#define POS_PER_BLOCK (P * CHUNKS)           // 64
#define NBLOCKS (NPOS / POS_PER_BLOCK)       // 512
#define SMEM_BYTES (2 * CHUNK_BYTES + 16)    // 2 stages + 2 mbarriers

// table sizes: 8 x n=2 then 8 x n=3
__constant__ unsigned int c_sizes[16] = {
    6619u, 6637u, 6653u, 6659u, 6661u, 6673u, 6679u, 6689u,
    65521u, 65537u, 65539u, 65543u, 65551u, 65557u, 65563u, 65579u
};

struct Tables { const float* t[16]; };

__device__ __forceinline__ uint32_t smem_u32(const void* p) {
    uint32_t a;
    asm("{ .reg .u64 tmp; cvta.to.shared.u64 tmp, %1; cvt.u32.u64 %0, tmp; }"
        : "=r"(a) : "l"(p));
    return a;
}

__device__ __forceinline__ void mbar_wait(uint32_t mbar, unsigned phase) {
    asm volatile(
        "{\n\t"
        ".reg .pred P1;\n\t"
        "W_%=:\n\t"
        "mbarrier.try_wait.parity.shared.b64 P1, [%0], %1, 0x989680;\n\t"
        "@P1 bra.uni D_%=;\n\t"
        "bra.uni W_%=;\n\t"
        "D_%=:\n\t"
        "}"
        :: "r"(mbar), "r"(phase) : "memory");
}

__global__ __launch_bounds__(THREADS) void engram_kernel(
    const int* __restrict__ ids,      // [B, S] int32
    const int* __restrict__ seeds,    // [3, 8] int32
    Tables tp,
    float* __restrict__ out)          // [B, S, 1280] fp32
{
    extern __shared__ __align__(16) unsigned char smem[];
    const uint32_t stage_a0 = smem_u32(smem);
    const uint32_t stage_a1 = stage_a0 + CHUNK_BYTES;
    const uint32_t mbar_a0  = stage_a0 + 2 * CHUNK_BYTES;
    const uint32_t mbar_a1  = mbar_a0 + 8;

    const int tid = threadIdx.x;
    if (tid == 0) {
        asm volatile("mbarrier.init.shared.b64 [%0], 1;" :: "r"(mbar_a0) : "memory");
        asm volatile("mbarrier.init.shared.b64 [%0], 1;" :: "r"(mbar_a1) : "memory");
    }
    __syncthreads();

    const int p    = tid >> 4;
    const int tab  = tid & 15;
    const int head = tab & 7;
    const int base = blockIdx.x * POS_PER_BLOCK;

    // hoist per-thread constants
    const unsigned long long sd0 = (unsigned int)seeds[head];
    const unsigned long long sd1 = (unsigned int)seeds[8 + head];
    const unsigned long long sd2 = (unsigned int)seeds[16 + head];
    const unsigned long long tsize = c_sizes[tab];
    const char* table = (const char*)tp.t[tab];

    // L2 policies: output writes evict-first; small hot n=2 tables evict-last
    uint64_t pol_ef, pol_el;
    asm("createpolicy.fractional.L2::evict_first.b64 %0, 1.0;" : "=l"(pol_ef));
    asm("createpolicy.fractional.L2::evict_last.b64 %0, 1.0;"  : "=l"(pol_el));
    const uint64_t ld_pol = (tab < 8) ? pol_el : pol_ef; // n3 reads barely re-hit: evict_first

    #pragma unroll 1
    for (int c = 0; c < CHUNKS; c++) {
        const int pos = base + c * P + p;
        const int s   = pos & (SEQ - 1);

        const unsigned long long id0 = (unsigned int)__ldg(ids + pos);
        const unsigned long long id1 =
            (s >= 1) ? (unsigned long long)(unsigned int)__ldg(ids + pos - 1) : 0ull;

        unsigned long long h;
        if (tab < 8) {
            h = (id1 * sd0) ^ (id0 * sd1);
        } else {
            const unsigned long long id2 =
                (s >= 2) ? (unsigned long long)(unsigned int)__ldg(ids + pos - 2) : 0ull;
            h = (id2 * sd0) ^ (id1 * sd1) ^ (id0 * sd2);
        }
        const unsigned int idx = (unsigned int)(h % tsize);

        // buffer reuse safety: store of chunk c-2 (same buffer) must have
        // finished READING its smem before we overwrite it
        if (c >= 2 && tid == 0) {
            asm volatile("cp.async.bulk.wait_group.read 0;" ::: "memory");
        }
        __syncthreads();

        const uint32_t stage_a = (c & 1) ? stage_a1 : stage_a0;
        const uint32_t mbar_a  = (c & 1) ? mbar_a1  : mbar_a0;

        const char*    src = table + (size_t)idx * ROW_BYTES;
        const uint32_t dst = stage_a + (uint32_t)tid * ROW_BYTES;
        asm volatile(
            "cp.async.bulk.shared::cta.global.mbarrier::complete_tx::bytes.L2::cache_hint "
            "[%0], [%1], %2, [%3], %4;"
            :: "r"(dst), "l"(src), "r"((int)ROW_BYTES), "r"(mbar_a), "l"(ld_pol)
            : "memory");
        if (tid == 0) {
            asm volatile("mbarrier.arrive.expect_tx.shared.b64 _, [%0], %1;"
                         :: "r"(mbar_a), "r"((int)CHUNK_BYTES) : "memory");
        }

        // drain previous chunk: wait its barrier, then one 40KB bulk store
        if (c >= 1 && tid == 0) {
            const int cp = c - 1;
            const uint32_t pm = (cp & 1) ? mbar_a1 : mbar_a0;
            const uint32_t ps = (cp & 1) ? stage_a1 : stage_a0;
            mbar_wait(pm, (unsigned)((cp >> 1) & 1));
            char* gdst = (char*)out + (size_t)(base + cp * P) * (NTAB * ROW_BYTES);
            asm volatile(
                "cp.async.bulk.global.shared::cta.bulk_group.L2::cache_hint "
                "[%0], [%1], %2, %3;"
                :: "l"(gdst), "r"(ps), "r"((int)CHUNK_BYTES), "l"(pol_ef)
                : "memory");
            asm volatile("cp.async.bulk.commit_group;" ::: "memory");
        }
    }

    // epilogue: store last chunk, then full drain before CTA exit
    if (tid == 0) {
        const int cp = CHUNKS - 1;
        const uint32_t pm = (cp & 1) ? mbar_a1 : mbar_a0;
        const uint32_t ps = (cp & 1) ? stage_a1 : stage_a0;
        mbar_wait(pm, (unsigned)((cp >> 1) & 1));
        char* gdst = (char*)out + (size_t)(base + cp * P) * (NTAB * ROW_BYTES);
        asm volatile(
            "cp.async.bulk.global.shared::cta.bulk_group.L2::cache_hint "
            "[%0], [%1], %2, %3;"
            :: "l"(gdst), "r"(ps), "r"((int)CHUNK_BYTES), "l"(pol_ef)
            : "memory");
        asm volatile("cp.async.bulk.commit_group;" ::: "memory");
        asm volatile("cp.async.bulk.wait_group 0;" ::: "memory");
    }
}

extern "C" void kernel_launch(void* const* d_in, const int* in_sizes, int n_in,
                              void* d_out, int out_size)
{
    const int* ids   = (const int*)d_in[0];
    const int* seeds = (const int*)d_in[1];

    Tables tp;
    #pragma unroll
    for (int i = 0; i < 16; i++) tp.t[i] = (const float*)d_in[2 + i];

    cudaFuncSetAttribute(engram_kernel,
                         cudaFuncAttributeMaxDynamicSharedMemorySize, SMEM_BYTES);
    engram_kernel<<<NBLOCKS, THREADS, SMEM_BYTES>>>(ids, seeds, tp, (float*)d_out);
}

// round 6
// speedup vs baseline: 3.3210x; 1.0048x over previous
#include <cuda_runtime.h>
#include <stdint.h>

#define SEQ   4096
#define NPOS  32768
#define SLOT  80
#define ROW_BYTES (SLOT * 4)                 // 320
#define NTAB  16
#define POS_BYTES (NTAB * ROW_BYTES)         // 5120 per position
#define P     4                              // positions per block
#define THREADS (P * NTAB)                   // 64
#define STAGE_BYTES (P * POS_BYTES)          // 20480
#define NBLOCKS (NPOS / P)                   // 8192

// table sizes: 8 x n=2 then 8 x n=3
__constant__ unsigned int c_sizes[16] = {
    6619u, 6637u, 6653u, 6659u, 6661u, 6673u, 6679u, 6689u,
    65521u, 65537u, 65539u, 65543u, 65551u, 65563u - 12u, 65579u  // placeholder fixed below
};

// NOTE: keep the real values (the line above must be exact) — define properly:
__constant__ unsigned int c_sizes_real[16] = {
    6619u, 6637u, 6653u, 6659u, 6661u, 6673u, 6679u, 6689u,
    65521u, 65537u, 65539u, 65543u, 65551u, 65557u, 65563u, 65579u
};

struct Tables { const float* t[16]; };

__device__ __forceinline__ uint32_t smem_u32(const void* p) {
    uint32_t a;
    asm("{ .reg .u64 tmp; cvta.to.shared.u64 tmp, %1; cvt.u32.u64 %0, tmp; }"
        : "=r"(a) : "l"(p));
    return a;
}

__global__ __launch_bounds__(THREADS) void engram_kernel(
    const int* __restrict__ ids,      // [B, S] int32
    const int* __restrict__ seeds,    // [3, 8] int32
    Tables tp,
    float* __restrict__ out)          // [B, S, 1280] fp32
{
    __shared__ __align__(16) unsigned char stage[STAGE_BYTES];
    __shared__ __align__(8)  unsigned long long mbar[P];

    const int tid = threadIdx.x;
    const uint32_t stage_a = smem_u32(stage);
    const uint32_t mbar_a0 = smem_u32(mbar);

    if (tid < P) {
        asm volatile("mbarrier.init.shared.b64 [%0], 1;"
                     :: "r"(mbar_a0 + tid * 8) : "memory");
    }
    __syncthreads();

    const int p    = tid >> 4;           // position within block
    const int tab  = tid & 15;           // table index
    const int head = tab & 7;
    const int pos  = blockIdx.x * P + p;
    const int s    = pos & (SEQ - 1);
    const uint32_t my_mbar = mbar_a0 + p * 8;

    // hash
    const unsigned long long id0 = (unsigned int)__ldg(ids + pos);
    const unsigned long long id1 =
        (s >= 1) ? (unsigned long long)(unsigned int)__ldg(ids + pos - 1) : 0ull;

    unsigned long long h;
    if (tab < 8) {
        h = (id1 * (unsigned long long)(unsigned int)__ldg(seeds + head))
          ^ (id0 * (unsigned long long)(unsigned int)__ldg(seeds + 8 + head));
    } else {
        const unsigned long long id2 =
            (s >= 2) ? (unsigned long long)(unsigned int)__ldg(ids + pos - 2) : 0ull;
        h = (id2 * (unsigned long long)(unsigned int)__ldg(seeds + head))
          ^ (id1 * (unsigned long long)(unsigned int)__ldg(seeds + 8 + head))
          ^ (id0 * (unsigned long long)(unsigned int)__ldg(seeds + 16 + head));
    }
    const unsigned int idx = (unsigned int)(h % (unsigned long long)c_sizes_real[tab]);

    // the drain thread for this position posts the expected byte count BEFORE
    // any load can complete? Not required: expect_tx may race with completions
    // as long as it's on the same barrier before the wait can succeed spuriously.
    // Post it first from the drain thread to be safe w.r.t. phase accounting.
    if (tab == 0) {
        asm volatile("mbarrier.arrive.expect_tx.shared.b64 _, [%0], %1;"
                     :: "r"(my_mbar), "r"((int)POS_BYTES) : "memory");
    }
    // all 16 threads of this position issue their row copy to the position barrier
    {
        const char*    src = (const char*)tp.t[tab] + (size_t)idx * ROW_BYTES;
        const uint32_t dst = stage_a + (uint32_t)tid * ROW_BYTES;  // (p*16+tab)*320
        asm volatile(
            "cp.async.bulk.shared::cta.global.mbarrier::complete_tx::bytes "
            "[%0], [%1], %2, [%3];"
            :: "r"(dst), "l"(src), "r"((int)ROW_BYTES), "r"(my_mbar)
            : "memory");
    }

    // per-position drain: as soon as this position's 5120B are in smem,
    // issue one contiguous 5KB bulk store. 4 independent drain threads.
    if (tab == 0) {
        asm volatile(
            "{\n\t"
            ".reg .pred P1;\n\t"
            "W_%=:\n\t"
            "mbarrier.try_wait.parity.shared.b64 P1, [%0], 0, 0x989680;\n\t"
            "@P1 bra.uni D_%=;\n\t"
            "bra.uni W_%=;\n\t"
            "D_%=:\n\t"
            "}"
            :: "r"(my_mbar) : "memory");

        char* gdst = (char*)out + (size_t)pos * POS_BYTES;
        asm volatile(
            "cp.async.bulk.global.shared::cta.bulk_group [%0], [%1], %2;"
            :: "l"(gdst), "r"(stage_a + (uint32_t)p * POS_BYTES), "r"((int)POS_BYTES)
            : "memory");
        asm volatile("cp.async.bulk.commit_group;" ::: "memory");
        // only wait until the store has READ smem (CTA slot may then recycle);
        // global write completion is guaranteed by kernel-end semantics.
        asm volatile("cp.async.bulk.wait_group.read 0;" ::: "memory");
    }
}

extern "C" void kernel_launch(void* const* d_in, const int* in_sizes, int n_in,
                              void* d_out, int out_size)
{
    const int* ids   = (const int*)d_in[0];
    const int* seeds = (const int*)d_in[1];

    Tables tp;
    #pragma unroll
    for (int i = 0; i < 16; i++) tp.t[i] = (const float*)d_in[2 + i];

    engram_kernel<<<NBLOCKS, THREADS>>>(ids, seeds, tp, (float*)d_out);
}

// round 7
// speedup vs baseline: 3.5539x; 1.0701x over previous
#include <cuda_runtime.h>
#include <stdint.h>

#define SEQ   4096
#define NPOS  32768
#define SLOT  80
#define ROW_BYTES (SLOT * 4)                 // 320
#define NTAB  16
#define POS_BYTES (NTAB * ROW_BYTES)         // 5120 per position
#define P     4                              // positions per block
#define THREADS (P * NTAB)                   // 64
#define STAGE_BYTES (P * POS_BYTES)          // 20480
#define NBLOCKS (NPOS / P)                   // 8192

// table sizes: 8 x n=2 then 8 x n=3
__constant__ unsigned int c_sizes[16] = {
    6619u, 6637u, 6653u, 6659u, 6661u, 6673u, 6679u, 6689u,
    65521u, 65537u, 65539u, 65543u, 65551u, 65557u, 65563u, 65579u
};

struct Tables { const float* t[16]; };

__device__ __forceinline__ uint32_t smem_u32(const void* p) {
    uint32_t a;
    asm("{ .reg .u64 tmp; cvta.to.shared.u64 tmp, %1; cvt.u32.u64 %0, tmp; }"
        : "=r"(a) : "l"(p));
    return a;
}

__global__ __launch_bounds__(THREADS) void engram_kernel(
    const int* __restrict__ ids,      // [B, S] int32
    const int* __restrict__ seeds,    // [3, 8] int32
    Tables tp,
    float* __restrict__ out)          // [B, S, 1280] fp32
{
    __shared__ __align__(16) unsigned char stage[STAGE_BYTES];
    __shared__ __align__(8)  unsigned long long mbar[P];

    const int tid = threadIdx.x;
    const uint32_t stage_a = smem_u32(stage);
    const uint32_t mbar_a0 = smem_u32(mbar);

    if (tid < P) {
        asm volatile("mbarrier.init.shared.b64 [%0], 1;"
                     :: "r"(mbar_a0 + tid * 8) : "memory");
    }
    __syncthreads();

    const int p    = tid >> 4;           // position within block
    const int tab  = tid & 15;           // table index
    const int head = tab & 7;
    const int pos  = blockIdx.x * P + p;
    const int s    = pos & (SEQ - 1);
    const uint32_t my_mbar = mbar_a0 + p * 8;

    // L2 policies:
    //  - output stores: evict_first (streaming; don't thrash read working set)
    //  - n3 gather loads: evict_last (unique set ~66MB fits L2; ~21% re-hits)
    uint64_t pol_ef, pol_el;
    asm("createpolicy.fractional.L2::evict_first.b64 %0, 1.0;" : "=l"(pol_ef));
    asm("createpolicy.fractional.L2::evict_last.b64 %0, 1.0;"  : "=l"(pol_el));

    // hash
    const unsigned long long id0 = (unsigned int)__ldg(ids + pos);
    const unsigned long long id1 =
        (s >= 1) ? (unsigned long long)(unsigned int)__ldg(ids + pos - 1) : 0ull;

    unsigned long long h;
    if (tab < 8) {
        h = (id1 * (unsigned long long)(unsigned int)__ldg(seeds + head))
          ^ (id0 * (unsigned long long)(unsigned int)__ldg(seeds + 8 + head));
    } else {
        const unsigned long long id2 =
            (s >= 2) ? (unsigned long long)(unsigned int)__ldg(ids + pos - 2) : 0ull;
        h = (id2 * (unsigned long long)(unsigned int)__ldg(seeds + head))
          ^ (id1 * (unsigned long long)(unsigned int)__ldg(seeds + 8 + head))
          ^ (id0 * (unsigned long long)(unsigned int)__ldg(seeds + 16 + head));
    }
    const unsigned int idx = (unsigned int)(h % (unsigned long long)c_sizes[tab]);

    // drain thread posts the expected byte count for this position's barrier
    if (tab == 0) {
        asm volatile("mbarrier.arrive.expect_tx.shared.b64 _, [%0], %1;"
                     :: "r"(my_mbar), "r"((int)POS_BYTES) : "memory");
    }
    // all 16 threads of this position issue their row copy to the position barrier
    {
        const char*    src = (const char*)tp.t[tab] + (size_t)idx * ROW_BYTES;
        const uint32_t dst = stage_a + (uint32_t)tid * ROW_BYTES;  // (p*16+tab)*320
        asm volatile(
            "cp.async.bulk.shared::cta.global.mbarrier::complete_tx::bytes.L2::cache_hint "
            "[%0], [%1], %2, [%3], %4;"
            :: "r"(dst), "l"(src), "r"((int)ROW_BYTES), "r"(my_mbar), "l"(pol_el)
            : "memory");
    }

    // per-position drain: as soon as this position's 5120B are in smem,
    // issue one contiguous 5KB bulk store. 4 independent drain threads.
    if (tab == 0) {
        asm volatile(
            "{\n\t"
            ".reg .pred P1;\n\t"
            "W_%=:\n\t"
            "mbarrier.try_wait.parity.shared.b64 P1, [%0], 0, 0x989680;\n\t"
            "@P1 bra.uni D_%=;\n\t"
            "bra.uni W_%=;\n\t"
            "D_%=:\n\t"
            "}"
            :: "r"(my_mbar) : "memory");

        char* gdst = (char*)out + (size_t)pos * POS_BYTES;
        asm volatile(
            "cp.async.bulk.global.shared::cta.bulk_group.L2::cache_hint "
            "[%0], [%1], %2, %3;"
            :: "l"(gdst), "r"(stage_a + (uint32_t)p * POS_BYTES), "r"((int)POS_BYTES),
               "l"(pol_ef)
            : "memory");
        asm volatile("cp.async.bulk.commit_group;" ::: "memory");
        // only wait until the store has READ smem (CTA slot may then recycle);
        // global write completion is guaranteed by kernel-end semantics.
        asm volatile("cp.async.bulk.wait_group.read 0;" ::: "memory");
    }
}

extern "C" void kernel_launch(void* const* d_in, const int* in_sizes, int n_in,
                              void* d_out, int out_size)
{
    const int* ids   = (const int*)d_in[0];
    const int* seeds = (const int*)d_in[1];

    Tables tp;
    #pragma unroll
    for (int i = 0; i < 16; i++) tp.t[i] = (const float*)d_in[2 + i];

    engram_kernel<<<NBLOCKS, THREADS>>>(ids, seeds, tp, (float*)d_out);
}